// round 6
// baseline (speedup 1.0000x reference)
#include <cuda_runtime.h>
#include <math.h>
#include <stdint.h>

#define PI_F      3.14159265358979323846f
#define TWO_PI_F  6.28318530717958647692f
#define N_NEUR    512
#define GW        (PI_F / 4.0f)
#define NSLICE    148                      // p-slices (one per SM)
#define NBLK      (NSLICE * 2)             // 2 blocks per SM (n-halves)
#define NT        256                      // threads per block
#define DEPTH     3
#define NL        30
#define SLAB_FLOATS (N_NEUR * NL)          // 15360 floats per p
#define HALF_FLOATS (NT * NL)              // 7680 floats per chunk (256 rows)
#define HALF_BYTES  (HALF_FLOATS * 4)      // 30720 bytes
#define MAX_M     80                       // >= ceil(10000/148)

// Scratch (static device memory; no allocations anywhere)
__device__ float g_partial[NSLICE * N_NEUR];
__device__ int   g_count = 0;

__device__ __forceinline__ float period_bound(float d) {
    float m = fmodf(d + PI_F, TWO_PI_F);
    if (m < 0.0f) m += TWO_PI_F;
    return m - PI_F;
}

__device__ __forceinline__ uint32_t smem_u32(const void* p) {
    return (uint32_t)__cvta_generic_to_shared(p);
}
__device__ __forceinline__ void mbar_init(uint32_t mb, uint32_t count) {
    asm volatile("mbarrier.init.shared.b64 [%0], %1;" :: "r"(mb), "r"(count) : "memory");
}
__device__ __forceinline__ void mbar_arrive(uint32_t mb) {
    asm volatile("mbarrier.arrive.shared.b64 _, [%0];" :: "r"(mb) : "memory");
}
__device__ __forceinline__ void bulk_load(uint32_t dst_smem, const void* src_gmem,
                                          uint32_t bytes, uint32_t mb) {
    asm volatile("mbarrier.arrive.expect_tx.shared.b64 _, [%0], %1;"
                 :: "r"(mb), "r"(bytes) : "memory");
    asm volatile("cp.async.bulk.shared::cluster.global.mbarrier::complete_tx::bytes "
                 "[%0], [%1], %2, [%3];"
                 :: "r"(dst_smem), "l"(src_gmem), "r"(bytes), "r"(mb) : "memory");
}
__device__ __forceinline__ void mbar_wait(uint32_t mb, uint32_t parity) {
    asm volatile(
        "{\n\t"
        ".reg .pred p;\n\t"
        "WL_%=:\n\t"
        "mbarrier.try_wait.parity.shared.b64 p, [%0], %1;\n\t"
        "@!p bra WL_%=;\n\t"
        "}"
        :: "r"(mb), "r"(parity) : "memory");
}

// ---------------------------------------------------------------------------
// Fused persistent kernel, 296 blocks x 256 threads (2 blocks/SM).
// Block b: p-slice = b>>1, n-half = b&1. Streams half-slabs (30720B) via
// cp.async.bulk with a full/empty mbarrier ring (consumers never block on the
// refill path; only thread 0 waits for the empty barrier).
// Thread t owns row t of its half: acc = sum_p w_p * dot(conn[p, row, :], rb).
// Last block finishes the whole ODE / convolution stage (2 neurons/thread).
// ---------------------------------------------------------------------------
__global__ void __launch_bounds__(NT, 2) fused_kernel(
    const float* __restrict__ conn,      // (P, 512, 30)
    const float* __restrict__ r,
    const float* __restrict__ u,
    const float* __restrict__ v,
    const float* __restrict__ r_hpc,     // (P,)
    const float* __restrict__ r_bearing, // (30,)
    const float* __restrict__ pos_estimate,
    const float* __restrict__ angular_velocity,
    const float* __restrict__ sen2hd,
    const float* __restrict__ shared_t,
    float* __restrict__ out,
    int P)
{
    extern __shared__ float buf[];                    // DEPTH * HALF_FLOATS
    __shared__ __align__(8) unsigned long long full_mb[DEPTH];
    __shared__ __align__(8) unsigned long long empty_mb[DEPTH];
    __shared__ float s_w[MAX_M];
    __shared__ int   s_last;
    __shared__ float s_red[NT];
    __shared__ float s_rr[N_NEUR];
    __shared__ float s_cn[N_NEUR];

    const int tid   = threadIdx.x;
    const int bid   = blockIdx.x;
    const int slice = bid >> 1;
    const int half  = bid & 1;

    // rb into registers (uniform; compile-time indices)
    float rbv[NL];
    #pragma unroll
    for (int l = 0; l < NL; l++) rbv[l] = __ldg(r_bearing + l);

    if (tid == 0) {
        #pragma unroll
        for (int s = 0; s < DEPTH; s++) {
            mbar_init(smem_u32(&full_mb[s]), 1u);      // 1 arrival: expect_tx
            mbar_init(smem_u32(&empty_mb[s]), (uint32_t)NT);
        }
    }

    const int begin = (int)(((long long)slice * P) / NSLICE);
    const int end   = (int)(((long long)(slice + 1) * P) / NSLICE);
    const int M     = end - begin;

    for (int i = tid; i < M; i += NT) s_w[i] = __ldg(r_hpc + begin + i);
    __syncthreads();  // barriers initialized + s_w visible

    if (tid == 0) {
        const int npro = M < DEPTH ? M : DEPTH;
        for (int s = 0; s < npro; s++) {
            bulk_load(smem_u32(buf + s * HALF_FLOATS),
                      conn + (size_t)(begin + s) * SLAB_FLOATS + half * HALF_FLOATS,
                      HALF_BYTES, smem_u32(&full_mb[s]));
        }
    }

    float acc = 0.0f;
    for (int i = 0; i < M; i++) {
        const int s  = i % DEPTH;
        const uint32_t ph = (uint32_t)((i / DEPTH) & 1);

        mbar_wait(smem_u32(&full_mb[s]), ph);

        const float2* row = (const float2*)(buf + s * HALF_FLOATS) + tid * (NL / 2);
        float dot = 0.0f;
        #pragma unroll
        for (int l = 0; l < NL / 2; l++) {
            float2 v2 = row[l];
            dot = fmaf(v2.x, rbv[2 * l],     dot);
            dot = fmaf(v2.y, rbv[2 * l + 1], dot);
        }
        acc = fmaf(s_w[i], dot, acc);

        mbar_arrive(smem_u32(&empty_mb[s]));          // non-blocking release

        if (tid == 0 && i + DEPTH < M) {
            // wait until all NT consumers released this slot, then refill
            mbar_wait(smem_u32(&empty_mb[s]), ph);
            bulk_load(smem_u32(buf + s * HALF_FLOATS),
                      conn + (size_t)(begin + i + DEPTH) * SLAB_FLOATS + half * HALF_FLOATS,
                      HALF_BYTES, smem_u32(&full_mb[s]));
        }
    }

    // publish partial (threadFenceReduction pattern)
    g_partial[slice * N_NEUR + half * NT + tid] = acc;
    __threadfence();
    __syncthreads();
    if (tid == 0) {
        int old = atomicAdd(&g_count, 1);
        s_last = (old == NBLK - 1);
    }
    __syncthreads();
    if (!s_last) return;

    // ------------------- last block: finish everything -------------------
    __threadfence();  // acquire all blocks' partials

    const int n0 = tid;
    const int n1 = tid + NT;

    // bearing reduction across slices (coalesced, mostly L2 hits)
    float bear0 = 0.0f, bear1 = 0.0f;
    #pragma unroll 4
    for (int sI = 0; sI < NSLICE; sI++) {
        bear0 += g_partial[sI * N_NEUR + n0];
        bear1 += g_partial[sI * N_NEUR + n1];
    }

    // sum(r_hpc)
    float sh = 0.0f;
    for (int i = tid; i < P; i += NT) sh += __ldg(r_hpc + i);
    s_red[tid] = sh;
    __syncthreads();
    #pragma unroll
    for (int off = NT / 2; off > 0; off >>= 1) {
        if (tid < off) s_red[tid] += s_red[tid + off];
        __syncthreads();
    }
    const float sum_hpc = s_red[0];
    __syncthreads();

    const float DX   = TWO_PI_F / 512.0f;
    const float J0   = 20.0f / 512.0f;
    const float KPAR = 0.8f / 512.0f * 20.0f;

    const float xn0 = -PI_F + n0 * DX;
    const float xn1 = -PI_F + n1 * DX;
    const float rn0 = r[n0];
    const float rn1 = r[n1];
    s_rr[n0] = rn0;
    s_rr[n1] = rn1;
    {
        float dj0 = period_bound(n0 * DX);
        float dj1 = period_bound(n1 * DX);
        float q0 = dj0 / GW, q1 = dj1 / GW;
        const float cnorm = 1.0f / (TWO_PI_F * GW * GW);
        s_cn[n0] = J0 * expf(-0.5f * q0 * q0) * cnorm;
        s_cn[n1] = J0 * expf(-0.5f * q1 * q1) * cnorm;
    }

    // bump center: angle(sum exp(i x) r)
    s_red[tid] = cosf(xn0) * rn0 + cosf(xn1) * rn1;
    __syncthreads();
    #pragma unroll
    for (int off = NT / 2; off > 0; off >>= 1) {
        if (tid < off) s_red[tid] += s_red[tid + off];
        __syncthreads();
    }
    const float csum = s_red[0];
    __syncthreads();
    s_red[tid] = sinf(xn0) * rn0 + sinf(xn1) * rn1;
    __syncthreads();
    #pragma unroll
    for (int off = NT / 2; off > 0; off >>= 1) {
        if (tid < off) s_red[tid] += s_red[tid + off];
        __syncthreads();
    }
    const float ssum = s_red[0];
    __syncthreads();
    const float center = atan2f(ssum, csum);

    // path integration (DT = 0.1 config constant, TAU_E = 1000)
    float pos = pos_estimate[0];
    float pe  = pos + (period_bound(center - pos) / 1000.0f + angular_velocity[0]) * 0.1f;
    pos = period_bound(pe);

    float dd0 = period_bound(xn0 - pos) / GW;
    float dd1 = period_bound(xn1 - pos) / GW;
    const float motion0 = 3.0f * expf(-0.25f * dd0 * dd0);
    const float motion1 = 3.0f * expf(-0.25f * dd1 * dd1);

    // recurrent input: circular convolution (both neurons per thread)
    float irec0 = 0.0f, irec1 = 0.0f;
    #pragma unroll 8
    for (int m = 0; m < N_NEUR; m++) {
        const float c = s_cn[m];
        irec0 = fmaf(c, s_rr[(n0 - m) & (N_NEUR - 1)], irec0);
        irec1 = fmaf(c, s_rr[(n1 - m) & (N_NEUR - 1)], irec1);
    }

    const float se = sen2hd[0];
    const float it0 = motion0 + irec0 + (bear0 / sum_hpc) * se;
    const float it1 = motion1 + irec1 + (bear1 / sum_hpc) * se;

    // exact exponential ODE step for u (v1 never feeds the output)
    const float dt_ode = shared_t[1] - shared_t[0];
    const float edt = expf(-dt_ode /* / TAU=1 */);
    const float C10 = it0 - v[n0];
    const float C11 = it1 - v[n1];
    const float u10 = C10 + (u[n0] - C10) * edt;
    const float u11 = C11 + (u[n1] - C11) * edt;

    const float un0 = u10 > 0.0f ? u10 : 0.0f;
    const float un1 = u11 > 0.0f ? u11 : 0.0f;
    const float r10 = un0 * un0;
    const float r11 = un1 * un1;

    s_red[tid] = r10 + r11;
    __syncthreads();
    #pragma unroll
    for (int off = NT / 2; off > 0; off >>= 1) {
        if (tid < off) s_red[tid] += s_red[tid + off];
        __syncthreads();
    }
    const float denom = 1.0f / (1.0f + KPAR * s_red[0]);

    out[n0] = r10 * denom;
    out[n1] = r11 * denom;

    if (tid == 0) g_count = 0;   // reset for next graph replay
}

// ---------------------------------------------------------------------------
// Launch
// ---------------------------------------------------------------------------
extern "C" void kernel_launch(void* const* d_in, const int* in_sizes, int n_in,
                              void* d_out, int out_size) {
    const float* conn      = (const float*)d_in[0];   // (P, 512, 30)
    const float* r         = (const float*)d_in[1];   // (512,)
    const float* u         = (const float*)d_in[2];   // (512,)
    const float* v         = (const float*)d_in[3];   // (512,)
    const float* r_hpc     = (const float*)d_in[4];   // (P,)
    const float* r_bearing = (const float*)d_in[5];   // (30,)
    const float* pos_est   = (const float*)d_in[6];   // (1,)
    const float* ang_vel   = (const float*)d_in[7];   // (1,)
    // d_in[8] = HD, unused (get_HD = 0 path)
    const float* sen2hd    = (const float*)d_in[9];   // (1,)
    const float* shared_t  = (const float*)d_in[10];  // (2,)
    float* out = (float*)d_out;

    const int P = in_sizes[4];  // r_hpc length

    const int smem_bytes = DEPTH * HALF_BYTES;  // 92160 per block
    cudaFuncSetAttribute(fused_kernel,
                         cudaFuncAttributeMaxDynamicSharedMemorySize, smem_bytes);

    fused_kernel<<<NBLK, NT, smem_bytes>>>(
        conn, r, u, v, r_hpc, r_bearing, pos_est, ang_vel, sen2hd, shared_t,
        out, P);
}

// round 7
// speedup vs baseline: 1.0542x; 1.0542x over previous
#include <cuda_runtime.h>
#include <math.h>
#include <stdint.h>

#define PI_F      3.14159265358979323846f
#define TWO_PI_F  6.28318530717958647692f
#define N_NEUR    512
#define GW        (PI_F / 4.0f)
#define NSLICE    148                      // one block per SM
#define NCONS     512                      // consumer threads (thread-per-row)
#define NWARPS_C  (NCONS / 32)             // 16 consumer warps
#define NT        (NCONS + 32)             // + 1 producer warp
#define DEPTH     3
#define NL        30
#define SLAB_FLOATS (N_NEUR * NL)          // 15360 floats per p
#define SLAB_BYTES  (SLAB_FLOATS * 4)      // 61440 bytes
#define MAX_M     80                       // >= ceil(10000/148)

// Scratch (static device memory; no allocations anywhere)
__device__ float g_partial[NSLICE * N_NEUR];
__device__ int   g_count = 0;

__device__ __forceinline__ float period_bound(float d) {
    float m = fmodf(d + PI_F, TWO_PI_F);
    if (m < 0.0f) m += TWO_PI_F;
    return m - PI_F;
}

__device__ __forceinline__ uint32_t smem_u32(const void* p) {
    return (uint32_t)__cvta_generic_to_shared(p);
}
__device__ __forceinline__ void mbar_init(uint32_t mb, uint32_t count) {
    asm volatile("mbarrier.init.shared.b64 [%0], %1;" :: "r"(mb), "r"(count) : "memory");
}
__device__ __forceinline__ void mbar_arrive(uint32_t mb) {
    asm volatile("mbarrier.arrive.shared.b64 _, [%0];" :: "r"(mb) : "memory");
}
__device__ __forceinline__ void bulk_load(uint32_t dst_smem, const void* src_gmem,
                                          uint32_t bytes, uint32_t mb) {
    asm volatile("mbarrier.arrive.expect_tx.shared.b64 _, [%0], %1;"
                 :: "r"(mb), "r"(bytes) : "memory");
    asm volatile("cp.async.bulk.shared::cluster.global.mbarrier::complete_tx::bytes "
                 "[%0], [%1], %2, [%3];"
                 :: "r"(dst_smem), "l"(src_gmem), "r"(bytes), "r"(mb) : "memory");
}
__device__ __forceinline__ void mbar_wait(uint32_t mb, uint32_t parity) {
    asm volatile(
        "{\n\t"
        ".reg .pred p;\n\t"
        "WL_%=:\n\t"
        "mbarrier.try_wait.parity.shared.b64 p, [%0], %1;\n\t"
        "@!p bra WL_%=;\n\t"
        "}"
        :: "r"(mb), "r"(parity) : "memory");
}

// ---------------------------------------------------------------------------
// Fused persistent kernel: 148 blocks x 544 threads (512 consumers + 1
// producer warp). Producer streams full 61440B p-slabs via cp.async.bulk into
// a DEPTH=3 ring, gated only by the per-slot empty barrier (16 warp-arrivals).
// Consumers free-run: wait full[s], dot(row, rb), one arrive per warp on
// empty[s] — no block-wide sync anywhere in the hot loop.
// Last block (threadFenceReduction) finishes the ODE / convolution stage.
// ---------------------------------------------------------------------------
__global__ void __launch_bounds__(NT, 1) fused_kernel(
    const float* __restrict__ conn,      // (P, 512, 30)
    const float* __restrict__ r,
    const float* __restrict__ u,
    const float* __restrict__ v,
    const float* __restrict__ r_hpc,     // (P,)
    const float* __restrict__ r_bearing, // (30,)
    const float* __restrict__ pos_estimate,
    const float* __restrict__ angular_velocity,
    const float* __restrict__ sen2hd,
    const float* __restrict__ shared_t,
    float* __restrict__ out,
    int P)
{
    extern __shared__ float buf[];                    // DEPTH * SLAB_FLOATS
    __shared__ __align__(8) unsigned long long full_mb[DEPTH];
    __shared__ __align__(8) unsigned long long empty_mb[DEPTH];
    __shared__ float s_w[MAX_M];
    __shared__ int   s_last;
    __shared__ float s_red[N_NEUR];
    __shared__ float s_rr[N_NEUR];
    __shared__ float s_cn[N_NEUR];

    const int tid = threadIdx.x;
    const int bid = blockIdx.x;

    if (tid == 0) {
        #pragma unroll
        for (int s = 0; s < DEPTH; s++) {
            mbar_init(smem_u32(&full_mb[s]), 1u);            // expect_tx only
            mbar_init(smem_u32(&empty_mb[s]), (uint32_t)NWARPS_C);
        }
    }

    const int begin = (int)(((long long)bid * P) / NSLICE);
    const int end   = (int)(((long long)(bid + 1) * P) / NSLICE);
    const int M     = end - begin;

    for (int i = tid; i < M; i += NT) s_w[i] = __ldg(r_hpc + begin + i);
    __syncthreads();  // barriers initialized + s_w visible to all

    if (tid < NCONS) {
        // ---------------- consumers ----------------
        float rbv[NL];
        #pragma unroll
        for (int l = 0; l < NL; l++) rbv[l] = __ldg(r_bearing + l);

        float acc = 0.0f;
        for (int i = 0; i < M; i++) {
            const int s = i % DEPTH;
            mbar_wait(smem_u32(&full_mb[s]), (uint32_t)((i / DEPTH) & 1));

            const float2* row = (const float2*)(buf + s * SLAB_FLOATS) + tid * (NL / 2);
            float dot = 0.0f;
            #pragma unroll
            for (int l = 0; l < NL / 2; l++) {
                float2 v2 = row[l];
                dot = fmaf(v2.x, rbv[2 * l],     dot);
                dot = fmaf(v2.y, rbv[2 * l + 1], dot);
            }
            acc = fmaf(s_w[i], dot, acc);

            __syncwarp();
            if ((tid & 31) == 0) mbar_arrive(smem_u32(&empty_mb[s]));
        }
        g_partial[bid * N_NEUR + tid] = acc;
    } else if (tid == NCONS) {
        // ---------------- producer (single thread of dedicated warp) -------
        const int npro = M < DEPTH ? M : DEPTH;
        for (int s = 0; s < npro; s++) {
            bulk_load(smem_u32(buf + s * SLAB_FLOATS),
                      conn + (size_t)(begin + s) * SLAB_FLOATS,
                      SLAB_BYTES, smem_u32(&full_mb[s]));
        }
        for (int i = DEPTH; i < M; i++) {
            const int s = i % DEPTH;
            // slot s last released at iteration i - DEPTH
            mbar_wait(smem_u32(&empty_mb[s]), (uint32_t)(((i / DEPTH) - 1) & 1));
            bulk_load(smem_u32(buf + s * SLAB_FLOATS),
                      conn + (size_t)(begin + i) * SLAB_FLOATS,
                      SLAB_BYTES, smem_u32(&full_mb[s]));
        }
    }

    // publish partial (threadFenceReduction pattern)
    __threadfence();
    __syncthreads();
    if (tid == 0) {
        int old = atomicAdd(&g_count, 1);
        s_last = (old == NSLICE - 1);
    }
    __syncthreads();
    if (!s_last) return;

    // ------------------- last block: finish everything -------------------
    __threadfence();  // acquire all blocks' partials

    const int n = tid;            // threads 512..543 idle through barriers
    const bool act = (n < N_NEUR);

    float bear = 0.0f;
    if (act) {
        float b0 = 0.f, b1 = 0.f, b2 = 0.f, b3 = 0.f;
        int sI = 0;
        for (; sI + 4 <= NSLICE; sI += 4) {
            b0 += g_partial[(sI + 0) * N_NEUR + n];
            b1 += g_partial[(sI + 1) * N_NEUR + n];
            b2 += g_partial[(sI + 2) * N_NEUR + n];
            b3 += g_partial[(sI + 3) * N_NEUR + n];
        }
        bear = (b0 + b1) + (b2 + b3);
    }

    // sum(r_hpc)
    {
        float sh = 0.0f;
        if (act) for (int i = n; i < P; i += N_NEUR) sh += __ldg(r_hpc + i);
        if (act) s_red[n] = sh;
    }
    __syncthreads();
    #pragma unroll
    for (int off = 256; off > 0; off >>= 1) {
        if (n < off) s_red[n] += s_red[n + off];
        __syncthreads();
    }
    const float sum_hpc = s_red[0];
    __syncthreads();

    const float DX   = TWO_PI_F / 512.0f;
    const float J0   = 20.0f / 512.0f;
    const float KPAR = 0.8f / 512.0f * 20.0f;

    const float xn = -PI_F + n * DX;
    float rn = 0.0f;
    if (act) {
        rn = r[n];
        s_rr[n] = rn;
        float dj = period_bound(n * DX);
        float q  = dj / GW;
        s_cn[n] = J0 * expf(-0.5f * q * q) / (TWO_PI_F * GW * GW);
    }

    // bump center: angle(sum exp(i x) r)
    if (act) s_red[n] = cosf(xn) * rn;
    __syncthreads();
    #pragma unroll
    for (int off = 256; off > 0; off >>= 1) {
        if (n < off) s_red[n] += s_red[n + off];
        __syncthreads();
    }
    const float csum = s_red[0];
    __syncthreads();
    if (act) s_red[n] = sinf(xn) * rn;
    __syncthreads();
    #pragma unroll
    for (int off = 256; off > 0; off >>= 1) {
        if (n < off) s_red[n] += s_red[n + off];
        __syncthreads();
    }
    const float ssum = s_red[0];
    __syncthreads();
    const float center = atan2f(ssum, csum);

    // path integration (DT = 0.1 config constant, TAU_E = 1000)
    float pos = pos_estimate[0];
    float pe  = pos + (period_bound(center - pos) / 1000.0f + angular_velocity[0]) * 0.1f;
    pos = period_bound(pe);

    float r1 = 0.0f;
    if (act) {
        float dd = period_bound(xn - pos) / GW;
        const float motion = 3.0f * expf(-0.25f * dd * dd);

        // recurrent input: circular convolution
        float irec = 0.0f;
        #pragma unroll 8
        for (int m = 0; m < N_NEUR; m++)
            irec = fmaf(s_cn[m], s_rr[(n - m) & (N_NEUR - 1)], irec);

        const float ib = bear / sum_hpc;
        const float input_total = motion + irec + ib * sen2hd[0];

        // exact exponential ODE step for u (v1 never feeds the output)
        const float dt_ode = shared_t[1] - shared_t[0];
        const float C1 = input_total - v[n];
        const float u1 = C1 + (u[n] - C1) * expf(-dt_ode /* / TAU=1 */);

        const float un = u1 > 0.0f ? u1 : 0.0f;
        r1 = un * un;
        s_red[n] = r1;
    }
    __syncthreads();
    #pragma unroll
    for (int off = 256; off > 0; off >>= 1) {
        if (n < off) s_red[n] += s_red[n + off];
        __syncthreads();
    }
    if (act) out[n] = r1 / (1.0f + KPAR * s_red[0]);

    if (tid == 0) g_count = 0;   // reset for next graph replay
}

// ---------------------------------------------------------------------------
// Launch
// ---------------------------------------------------------------------------
extern "C" void kernel_launch(void* const* d_in, const int* in_sizes, int n_in,
                              void* d_out, int out_size) {
    const float* conn      = (const float*)d_in[0];   // (P, 512, 30)
    const float* r         = (const float*)d_in[1];   // (512,)
    const float* u         = (const float*)d_in[2];   // (512,)
    const float* v         = (const float*)d_in[3];   // (512,)
    const float* r_hpc     = (const float*)d_in[4];   // (P,)
    const float* r_bearing = (const float*)d_in[5];   // (30,)
    const float* pos_est   = (const float*)d_in[6];   // (1,)
    const float* ang_vel   = (const float*)d_in[7];   // (1,)
    // d_in[8] = HD, unused (get_HD = 0 path)
    const float* sen2hd    = (const float*)d_in[9];   // (1,)
    const float* shared_t  = (const float*)d_in[10];  // (2,)
    float* out = (float*)d_out;

    const int P = in_sizes[4];  // r_hpc length

    const int smem_bytes = DEPTH * SLAB_BYTES;  // 184320 per block
    cudaFuncSetAttribute(fused_kernel,
                         cudaFuncAttributeMaxDynamicSharedMemorySize, smem_bytes);

    fused_kernel<<<NSLICE, NT, smem_bytes>>>(
        conn, r, u, v, r_hpc, r_bearing, pos_est, ang_vel, sen2hd, shared_t,
        out, P);
}

// round 9
// speedup vs baseline: 1.1163x; 1.0589x over previous
#include <cuda_runtime.h>
#include <math.h>
#include <stdint.h>

#define PI_F      3.14159265358979323846f
#define TWO_PI_F  6.28318530717958647692f
#define N_NEUR    512
#define GW        (PI_F / 4.0f)
#define GRID      148
#define DEPTH     3
#define NL        30
#define TG        4                        // slabs per stolen ticket
#define SLAB_FLOATS (N_NEUR * NL)          // 15360 floats
#define SLAB_BYTES  (SLAB_FLOATS * 4)      // 61440 bytes

// Scratch (static device memory; no allocations anywhere)
__device__ float g_partial[GRID * N_NEUR];
__device__ int   g_count  = 0;
__device__ int   g_ticket = 0;

__device__ __forceinline__ float period_bound(float d) {
    float m = fmodf(d + PI_F, TWO_PI_F);
    if (m < 0.0f) m += TWO_PI_F;
    return m - PI_F;
}

__device__ __forceinline__ uint32_t smem_u32(const void* p) {
    return (uint32_t)__cvta_generic_to_shared(p);
}
__device__ __forceinline__ void mbar_init(uint32_t mb, uint32_t count) {
    asm volatile("mbarrier.init.shared.b64 [%0], %1;" :: "r"(mb), "r"(count) : "memory");
}
__device__ __forceinline__ void bulk_load(uint32_t dst_smem, const void* src_gmem,
                                          uint32_t bytes, uint32_t mb) {
    asm volatile("mbarrier.arrive.expect_tx.shared.b64 _, [%0], %1;"
                 :: "r"(mb), "r"(bytes) : "memory");
    asm volatile("cp.async.bulk.shared::cluster.global.mbarrier::complete_tx::bytes "
                 "[%0], [%1], %2, [%3];"
                 :: "r"(dst_smem), "l"(src_gmem), "r"(bytes), "r"(mb) : "memory");
}
__device__ __forceinline__ void mbar_wait(uint32_t mb, uint32_t parity) {
    asm volatile(
        "{\n\t"
        ".reg .pred p;\n\t"
        "WL_%=:\n\t"
        "mbarrier.try_wait.parity.shared.b64 p, [%0], %1;\n\t"
        "@!p bra WL_%=;\n\t"
        "}"
        :: "r"(mb), "r"(parity) : "memory");
}

// ---------------------------------------------------------------------------
// Fused persistent kernel (R4 pipeline + dynamic work stealing).
//  148 blocks x 512 threads. Thread 0 steals tickets of TG=4 consecutive
//  p-slabs from g_ticket and streams them through a DEPTH=3 cp.async.bulk
//  ring. s_pidx[s] carries the slab index (-1 = no more work), written by
//  thread 0 during refill; DEPTH-1 >= 2 __syncthreads separate the write from
//  any consumer read. Thread n accumulates sum_p w_p * dot(conn[p,n,:], rb).
//  Last block (threadFenceReduction) runs the ODE / convolution stage and
//  resets the global counters for the next graph replay.
// ---------------------------------------------------------------------------
__global__ void __launch_bounds__(N_NEUR, 1) fused_kernel(
    const float* __restrict__ conn,      // (P, 512, 30)
    const float* __restrict__ r,
    const float* __restrict__ u,
    const float* __restrict__ v,
    const float* __restrict__ r_hpc,     // (P,)
    const float* __restrict__ r_bearing, // (30,)
    const float* __restrict__ pos_estimate,
    const float* __restrict__ angular_velocity,
    const float* __restrict__ sen2hd,
    const float* __restrict__ shared_t,
    float* __restrict__ out,
    int P)
{
    extern __shared__ float buf[];                 // DEPTH * SLAB_FLOATS
    __shared__ __align__(8) unsigned long long mbar[DEPTH];
    __shared__ int   s_pidx[DEPTH];
    __shared__ int   s_last;
    __shared__ float s_red[N_NEUR];
    __shared__ float s_rr[N_NEUR];
    __shared__ float s_cn[N_NEUR];

    const int tid = threadIdx.x;
    const int bid = blockIdx.x;

    // rb into registers (uniform; compile-time indices)
    float rbv[NL];
    #pragma unroll
    for (int l = 0; l < NL; l++) rbv[l] = __ldg(r_bearing + l);

    // ticket state lives in thread 0's registers
    int cur = 0, rem = 0;

    if (tid == 0) {
        #pragma unroll
        for (int s = 0; s < DEPTH; s++) mbar_init(smem_u32(&mbar[s]), 1u);
        // preload up to DEPTH slabs
        for (int s = 0; s < DEPTH; s++) {
            if (rem == 0) {
                cur = atomicAdd(&g_ticket, TG);
                rem = (cur < P) ? min(TG, P - cur) : 0;
            }
            if (rem > 0) {
                s_pidx[s] = cur;
                bulk_load(smem_u32(buf + s * SLAB_FLOATS),
                          conn + (size_t)cur * SLAB_FLOATS,
                          SLAB_BYTES, smem_u32(&mbar[s]));
                cur++; rem--;
            } else {
                s_pidx[s] = -1;
            }
        }
    }
    __syncthreads();  // barriers + preload indices visible

    float acc = 0.0f;
    for (int it = 0; ; it++) {
        const int s = it % DEPTH;
        const int p = s_pidx[s];      // written >= DEPTH-1 barriers ago
        if (p < 0) break;

        const float w = __ldg(r_hpc + p);     // broadcast load, issues early
        mbar_wait(smem_u32(&mbar[s]), (uint32_t)((it / DEPTH) & 1));

        const float2* row = (const float2*)(buf + s * SLAB_FLOATS) + tid * (NL / 2);
        float dot = 0.0f;
        #pragma unroll
        for (int l = 0; l < NL / 2; l++) {
            float2 v2 = row[l];
            dot = fmaf(v2.x, rbv[2 * l],     dot);
            dot = fmaf(v2.y, rbv[2 * l + 1], dot);
        }
        acc = fmaf(w, dot, acc);

        __syncthreads();              // everyone done with buf[s]
        if (tid == 0) {
            if (rem == 0) {
                cur = atomicAdd(&g_ticket, TG);
                rem = (cur < P) ? min(TG, P - cur) : 0;
            }
            if (rem > 0) {
                s_pidx[s] = cur;
                bulk_load(smem_u32(buf + s * SLAB_FLOATS),
                          conn + (size_t)cur * SLAB_FLOATS,
                          SLAB_BYTES, smem_u32(&mbar[s]));
                cur++; rem--;
            } else {
                s_pidx[s] = -1;
            }
        }
    }

    // publish partial (threadFenceReduction pattern)
    g_partial[bid * N_NEUR + tid] = acc;
    __threadfence();
    __syncthreads();
    if (tid == 0) {
        int old = atomicAdd(&g_count, 1);
        s_last = (old == GRID - 1);
    }
    __syncthreads();
    if (!s_last) return;

    // ------------------- last block: finish everything -------------------
    __threadfence();  // acquire all blocks' partials

    const int n = tid;

    // bearing reduction across blocks (coalesced, mostly L2 hits)
    float bear;
    {
        float b0 = 0.f, b1 = 0.f, b2 = 0.f, b3 = 0.f;
        #pragma unroll 
        for (int b = 0; b + 4 <= GRID; b += 4) {
            b0 += g_partial[(b + 0) * N_NEUR + n];
            b1 += g_partial[(b + 1) * N_NEUR + n];
            b2 += g_partial[(b + 2) * N_NEUR + n];
            b3 += g_partial[(b + 3) * N_NEUR + n];
        }
        bear = (b0 + b1) + (b2 + b3);
    }

    // sum(r_hpc)
    float sh = 0.0f;
    for (int i = n; i < P; i += N_NEUR) sh += __ldg(r_hpc + i);
    s_red[n] = sh;
    __syncthreads();
    #pragma unroll
    for (int off = 256; off > 0; off >>= 1) {
        if (n < off) s_red[n] += s_red[n + off];
        __syncthreads();
    }
    const float sum_hpc = s_red[0];
    __syncthreads();

    const float DX   = TWO_PI_F / 512.0f;
    const float J0   = 20.0f / 512.0f;
    const float KPAR = 0.8f / 512.0f * 20.0f;

    const float xn = -PI_F + n * DX;
    const float rn = r[n];
    s_rr[n] = rn;
    {
        float dj = period_bound(n * DX);
        float q  = dj / GW;
        s_cn[n] = J0 * expf(-0.5f * q * q) / (TWO_PI_F * GW * GW);
    }

    // bump center: angle(sum exp(i x) r)
    s_red[n] = cosf(xn) * rn;
    __syncthreads();
    #pragma unroll
    for (int off = 256; off > 0; off >>= 1) {
        if (n < off) s_red[n] += s_red[n + off];
        __syncthreads();
    }
    const float csum = s_red[0];
    __syncthreads();
    s_red[n] = sinf(xn) * rn;
    __syncthreads();
    #pragma unroll
    for (int off = 256; off > 0; off >>= 1) {
        if (n < off) s_red[n] += s_red[n + off];
        __syncthreads();
    }
    const float ssum = s_red[0];
    __syncthreads();
    const float center = atan2f(ssum, csum);

    // path integration (DT = 0.1 config constant, TAU_E = 1000)
    float pos = pos_estimate[0];
    float pe  = pos + (period_bound(center - pos) / 1000.0f + angular_velocity[0]) * 0.1f;
    pos = period_bound(pe);

    float dd = period_bound(xn - pos) / GW;
    const float motion = 3.0f * expf(-0.25f * dd * dd);

    // recurrent input: circular convolution
    float irec = 0.0f;
    #pragma unroll 8
    for (int m = 0; m < N_NEUR; m++)
        irec = fmaf(s_cn[m], s_rr[(n - m) & (N_NEUR - 1)], irec);

    const float ib = bear / sum_hpc;
    const float input_total = motion + irec + ib * sen2hd[0];

    // exact exponential ODE step for u (v1 never feeds the output)
    const float dt_ode = shared_t[1] - shared_t[0];
    const float C1 = input_total - v[n];
    const float u1 = C1 + (u[n] - C1) * expf(-dt_ode /* / TAU=1 */);

    const float un = u1 > 0.0f ? u1 : 0.0f;
    const float r1 = un * un;

    s_red[n] = r1;
    __syncthreads();
    #pragma unroll
    for (int off = 256; off > 0; off >>= 1) {
        if (n < off) s_red[n] += s_red[n + off];
        __syncthreads();
    }
    const float sum_r1 = s_red[0];

    out[n] = r1 / (1.0f + KPAR * sum_r1);

    if (n == 0) { g_count = 0; g_ticket = 0; }   // reset for next graph replay
}

// ---------------------------------------------------------------------------
// Launch
// ---------------------------------------------------------------------------
extern "C" void kernel_launch(void* const* d_in, const int* in_sizes, int n_in,
                              void* d_out, int out_size) {
    const float* conn      = (const float*)d_in[0];   // (P, 512, 30)
    const float* r         = (const float*)d_in[1];   // (512,)
    const float* u         = (const float*)d_in[2];   // (512,)
    const float* v         = (const float*)d_in[3];   // (512,)
    const float* r_hpc     = (const float*)d_in[4];   // (P,)
    const float* r_bearing = (const float*)d_in[5];   // (30,)
    const float* pos_est   = (const float*)d_in[6];   // (1,)
    const float* ang_vel   = (const float*)d_in[7];   // (1,)
    // d_in[8] = HD, unused (get_HD = 0 path)
    const float* sen2hd    = (const float*)d_in[9];   // (1,)
    const float* shared_t  = (const float*)d_in[10];  // (2,)
    float* out = (float*)d_out;

    const int P = in_sizes[4];  // r_hpc length

    const int smem_bytes = DEPTH * SLAB_BYTES;  // 184320 per block
    cudaFuncSetAttribute(fused_kernel,
                         cudaFuncAttributeMaxDynamicSharedMemorySize, smem_bytes);

    fused_kernel<<<GRID, N_NEUR, smem_bytes>>>(
        conn, r, u, v, r_hpc, r_bearing, pos_est, ang_vel, sen2hd, shared_t,
        out, P);
}

// round 12
// speedup vs baseline: 1.1413x; 1.0224x over previous
#include <cuda_runtime.h>
#include <math.h>
#include <stdint.h>

#define PI_F      3.14159265358979323846f
#define TWO_PI_F  6.28318530717958647692f
#define N_NEUR    512
#define GW        (PI_F / 4.0f)
#define GRID      148
#define DEPTH     3
#define NL        30
#define TG        4                        // slabs per stolen ticket
#define SLAB_FLOATS (N_NEUR * NL)          // 15360 floats
#define SLAB_BYTES  (SLAB_FLOATS * 4)      // 61440 bytes

// Scratch (static device memory, zero-initialized; no allocations anywhere)
__device__ float g_partial[GRID * N_NEUR];
__device__ float g_sum_hpc = 0.0f;
__device__ int   g_count  = 0;
__device__ int   g_ticket = 0;

__device__ __forceinline__ float period_bound(float d) {
    float m = fmodf(d + PI_F, TWO_PI_F);
    if (m < 0.0f) m += TWO_PI_F;
    return m - PI_F;
}

__device__ __forceinline__ uint32_t smem_u32(const void* p) {
    return (uint32_t)__cvta_generic_to_shared(p);
}
__device__ __forceinline__ void mbar_init(uint32_t mb, uint32_t count) {
    asm volatile("mbarrier.init.shared.b64 [%0], %1;" :: "r"(mb), "r"(count) : "memory");
}
__device__ __forceinline__ void bulk_load(uint32_t dst_smem, const void* src_gmem,
                                          uint32_t bytes, uint32_t mb) {
    asm volatile("mbarrier.arrive.expect_tx.shared.b64 _, [%0], %1;"
                 :: "r"(mb), "r"(bytes) : "memory");
    asm volatile("cp.async.bulk.shared::cluster.global.mbarrier::complete_tx::bytes "
                 "[%0], [%1], %2, [%3];"
                 :: "r"(dst_smem), "l"(src_gmem), "r"(bytes), "r"(mb) : "memory");
}
__device__ __forceinline__ void mbar_wait(uint32_t mb, uint32_t parity) {
    asm volatile(
        "{\n\t"
        ".reg .pred p;\n\t"
        "WL_%=:\n\t"
        "mbarrier.try_wait.parity.shared.b64 p, [%0], %1;\n\t"
        "@!p bra WL_%=;\n\t"
        "}"
        :: "r"(mb), "r"(parity) : "memory");
}

// ---------------------------------------------------------------------------
// Fused persistent kernel (R8 proven core + streamed sum(r_hpc)).
//  148 blocks x 512 threads, dynamic work stealing (TG=4 slabs/ticket),
//  DEPTH=3 cp.async.bulk ring gated by __syncthreads.
//  Thread n accumulates sum_p w_p * dot(conn[p,n,:], rb); thread 0 also
//  accumulates the block's share of sum(r_hpc) (ticket ranges partition P).
//  Last block (threadFenceReduction) reduces partials and runs the small
//  ODE / convolution stage; resets globals for the next graph replay.
// ---------------------------------------------------------------------------
__global__ void __launch_bounds__(N_NEUR, 1) fused_kernel(
    const float* __restrict__ conn,      // (P, 512, 30)
    const float* __restrict__ r,
    const float* __restrict__ u,
    const float* __restrict__ v,
    const float* __restrict__ r_hpc,     // (P,)
    const float* __restrict__ r_bearing, // (30,)
    const float* __restrict__ pos_estimate,
    const float* __restrict__ angular_velocity,
    const float* __restrict__ sen2hd,
    const float* __restrict__ shared_t,
    float* __restrict__ out,
    int P)
{
    extern __shared__ float buf[];                 // DEPTH * SLAB_FLOATS
    __shared__ __align__(8) unsigned long long mbar[DEPTH];
    __shared__ int   s_pidx[DEPTH];
    __shared__ int   s_last;
    __shared__ float s_red[N_NEUR];
    __shared__ float s_rr[N_NEUR];
    __shared__ float s_cn[N_NEUR];

    const int tid = threadIdx.x;
    const int bid = blockIdx.x;

    // rb into registers (uniform; compile-time indices)
    float rbv[NL];
    #pragma unroll
    for (int l = 0; l < NL; l++) rbv[l] = __ldg(r_bearing + l);

    // ticket state lives in thread 0's registers
    int cur = 0, rem = 0;

    if (tid == 0) {
        #pragma unroll
        for (int s = 0; s < DEPTH; s++) mbar_init(smem_u32(&mbar[s]), 1u);
        // preload up to DEPTH slabs
        for (int s = 0; s < DEPTH; s++) {
            if (rem == 0) {
                cur = atomicAdd(&g_ticket, TG);
                rem = (cur < P) ? min(TG, P - cur) : 0;
            }
            if (rem > 0) {
                s_pidx[s] = cur;
                bulk_load(smem_u32(buf + s * SLAB_FLOATS),
                          conn + (size_t)cur * SLAB_FLOATS,
                          SLAB_BYTES, smem_u32(&mbar[s]));
                cur++; rem--;
            } else {
                s_pidx[s] = -1;
            }
        }
    }
    __syncthreads();  // barriers + preload indices visible

    float acc  = 0.0f;
    float wsum = 0.0f;                    // thread 0 only: block's sum(r_hpc)
    for (int it = 0; ; it++) {
        const int s = it % DEPTH;
        const int p = s_pidx[s];          // written >= DEPTH-1 barriers ago
        if (p < 0) break;

        const float w = __ldg(r_hpc + p); // broadcast load, issues early
        if (tid == 0) wsum += w;          // p's are disjoint across blocks
        mbar_wait(smem_u32(&mbar[s]), (uint32_t)((it / DEPTH) & 1));

        const float2* row = (const float2*)(buf + s * SLAB_FLOATS) + tid * (NL / 2);
        float dot = 0.0f;
        #pragma unroll
        for (int l = 0; l < NL / 2; l++) {
            float2 v2 = row[l];
            dot = fmaf(v2.x, rbv[2 * l],     dot);
            dot = fmaf(v2.y, rbv[2 * l + 1], dot);
        }
        acc = fmaf(w, dot, acc);

        __syncthreads();                  // everyone done with buf[s]
        if (tid == 0) {
            if (rem == 0) {
                cur = atomicAdd(&g_ticket, TG);
                rem = (cur < P) ? min(TG, P - cur) : 0;
            }
            if (rem > 0) {
                s_pidx[s] = cur;
                bulk_load(smem_u32(buf + s * SLAB_FLOATS),
                          conn + (size_t)cur * SLAB_FLOATS,
                          SLAB_BYTES, smem_u32(&mbar[s]));
                cur++; rem--;
            } else {
                s_pidx[s] = -1;
            }
        }
    }

    // publish partial (threadFenceReduction pattern)
    g_partial[bid * N_NEUR + tid] = acc;
    if (tid == 0) atomicAdd(&g_sum_hpc, wsum);
    __threadfence();
    __syncthreads();
    if (tid == 0) {
        int old = atomicAdd(&g_count, 1);
        s_last = (old == GRID - 1);
    }
    __syncthreads();
    if (!s_last) return;

    // ------------------- last block: finish everything -------------------
    __threadfence();  // acquire all blocks' partials + g_sum_hpc

    const int n = tid;

    // bearing reduction across blocks (coalesced, mostly L2 hits)
    float bear;
    {
        float b0 = 0.f, b1 = 0.f, b2 = 0.f, b3 = 0.f;
        #pragma unroll
        for (int b = 0; b + 4 <= GRID; b += 4) {
            b0 += g_partial[(b + 0) * N_NEUR + n];
            b1 += g_partial[(b + 1) * N_NEUR + n];
            b2 += g_partial[(b + 2) * N_NEUR + n];
            b3 += g_partial[(b + 3) * N_NEUR + n];
        }
        bear = (b0 + b1) + (b2 + b3);
    }

    const float sum_hpc = g_sum_hpc;      // accumulated during streaming

    const float DX   = TWO_PI_F / 512.0f;
    const float J0   = 20.0f / 512.0f;
    const float KPAR = 0.8f / 512.0f * 20.0f;

    const float xn = -PI_F + n * DX;
    const float rn = r[n];
    s_rr[n] = rn;
    {
        float dj = period_bound(n * DX);
        float q  = dj / GW;
        s_cn[n] = J0 * expf(-0.5f * q * q) / (TWO_PI_F * GW * GW);
    }

    // bump center: angle(sum exp(i x) r)
    s_red[n] = cosf(xn) * rn;
    __syncthreads();
    #pragma unroll
    for (int off = 256; off > 0; off >>= 1) {
        if (n < off) s_red[n] += s_red[n + off];
        __syncthreads();
    }
    const float csum = s_red[0];
    __syncthreads();
    s_red[n] = sinf(xn) * rn;
    __syncthreads();
    #pragma unroll
    for (int off = 256; off > 0; off >>= 1) {
        if (n < off) s_red[n] += s_red[n + off];
        __syncthreads();
    }
    const float ssum = s_red[0];
    __syncthreads();
    const float center = atan2f(ssum, csum);

    // path integration (DT = 0.1 config constant, TAU_E = 1000)
    float pos = pos_estimate[0];
    float pe  = pos + (period_bound(center - pos) / 1000.0f + angular_velocity[0]) * 0.1f;
    pos = period_bound(pe);

    float dd = period_bound(xn - pos) / GW;
    const float motion = 3.0f * expf(-0.25f * dd * dd);

    // recurrent input: circular convolution
    float irec = 0.0f;
    #pragma unroll 8
    for (int m = 0; m < N_NEUR; m++)
        irec = fmaf(s_cn[m], s_rr[(n - m) & (N_NEUR - 1)], irec);

    const float ib = bear / sum_hpc;
    const float input_total = motion + irec + ib * sen2hd[0];

    // exact exponential ODE step for u (v1 never feeds the output)
    const float dt_ode = shared_t[1] - shared_t[0];
    const float C1 = input_total - v[n];
    const float u1 = C1 + (u[n] - C1) * expf(-dt_ode /* / TAU=1 */);

    const float un = u1 > 0.0f ? u1 : 0.0f;
    const float r1 = un * un;

    s_red[n] = r1;
    __syncthreads();
    #pragma unroll
    for (int off = 256; off > 0; off >>= 1) {
        if (n < off) s_red[n] += s_red[n + off];
        __syncthreads();
    }
    const float sum_r1 = s_red[0];

    out[n] = r1 / (1.0f + KPAR * sum_r1);

    // reset for next graph replay (all threads are past their g_sum_hpc read:
    // the block-wide reductions above synchronized the block)
    if (n == 0) { g_count = 0; g_ticket = 0; g_sum_hpc = 0.0f; }
}

// ---------------------------------------------------------------------------
// Launch
// ---------------------------------------------------------------------------
extern "C" void kernel_launch(void* const* d_in, const int* in_sizes, int n_in,
                              void* d_out, int out_size) {
    const float* conn      = (const float*)d_in[0];   // (P, 512, 30)
    const float* r         = (const float*)d_in[1];   // (512,)
    const float* u         = (const float*)d_in[2];   // (512,)
    const float* v         = (const float*)d_in[3];   // (512,)
    const float* r_hpc     = (const float*)d_in[4];   // (P,)
    const float* r_bearing = (const float*)d_in[5];   // (30,)
    const float* pos_est   = (const float*)d_in[6];   // (1,)
    const float* ang_vel   = (const float*)d_in[7];   // (1,)
    // d_in[8] = HD, unused (get_HD = 0 path)
    const float* sen2hd    = (const float*)d_in[9];   // (1,)
    const float* shared_t  = (const float*)d_in[10];  // (2,)
    float* out = (float*)d_out;

    const int P = in_sizes[4];  // r_hpc length

    const int smem_bytes = DEPTH * SLAB_BYTES;  // 184320 per block
    cudaFuncSetAttribute(fused_kernel,
                         cudaFuncAttributeMaxDynamicSharedMemorySize, smem_bytes);

    fused_kernel<<<GRID, N_NEUR, smem_bytes>>>(
        conn, r, u, v, r_hpc, r_bearing, pos_est, ang_vel, sen2hd, shared_t,
        out, P);
}

// round 13
// speedup vs baseline: 1.1534x; 1.0106x over previous
#include <cuda_runtime.h>
#include <math.h>
#include <stdint.h>

#define PI_F      3.14159265358979323846f
#define TWO_PI_F  6.28318530717958647692f
#define N_NEUR    512
#define GW        (PI_F / 4.0f)
#define GRID      148
#define DEPTH     3
#define NL        30
#define TG        4                        // slabs per stolen ticket
#define SLAB_FLOATS (N_NEUR * NL)          // 15360 floats
#define SLAB_BYTES  (SLAB_FLOATS * 4)      // 61440 bytes

// Scratch (static device memory, zero-initialized; no allocations anywhere)
__device__ float g_bearing[N_NEUR];        // accumulated across blocks
__device__ float g_sum_hpc = 0.0f;
__device__ int   g_count  = 0;
__device__ int   g_ticket = 0;

__device__ __forceinline__ float period_bound(float d) {
    float m = fmodf(d + PI_F, TWO_PI_F);
    if (m < 0.0f) m += TWO_PI_F;
    return m - PI_F;
}

__device__ __forceinline__ uint32_t smem_u32(const void* p) {
    return (uint32_t)__cvta_generic_to_shared(p);
}
__device__ __forceinline__ void mbar_init(uint32_t mb, uint32_t count) {
    asm volatile("mbarrier.init.shared.b64 [%0], %1;" :: "r"(mb), "r"(count) : "memory");
}
__device__ __forceinline__ void bulk_load(uint32_t dst_smem, const void* src_gmem,
                                          uint32_t bytes, uint32_t mb) {
    asm volatile("mbarrier.arrive.expect_tx.shared.b64 _, [%0], %1;"
                 :: "r"(mb), "r"(bytes) : "memory");
    asm volatile("cp.async.bulk.shared::cluster.global.mbarrier::complete_tx::bytes "
                 "[%0], [%1], %2, [%3];"
                 :: "r"(dst_smem), "l"(src_gmem), "r"(bytes), "r"(mb) : "memory");
}
__device__ __forceinline__ void mbar_wait(uint32_t mb, uint32_t parity) {
    asm volatile(
        "{\n\t"
        ".reg .pred p;\n\t"
        "WL_%=:\n\t"
        "mbarrier.try_wait.parity.shared.b64 p, [%0], %1;\n\t"
        "@!p bra WL_%=;\n\t"
        "}"
        :: "r"(mb), "r"(parity) : "memory");
}

// ---------------------------------------------------------------------------
// Fused persistent kernel (R11 proven core + distributed tail).
//  148 blocks x 512 threads, dynamic work stealing (TG=4 slabs/ticket),
//  DEPTH=3 cp.async.bulk ring gated by __syncthreads.
//  Thread n accumulates sum_p w_p * dot(conn[p,n,:], rb) and publishes it
//  directly into g_bearing[n] via one coalesced atomicAdd (overlapped with
//  other blocks' streaming). Thread 0 streams the block's share of
//  sum(r_hpc) (ticket ranges partition P). Last block only runs the small
//  ODE / convolution stage and resets globals for the next graph replay.
// ---------------------------------------------------------------------------
__global__ void __launch_bounds__(N_NEUR, 1) fused_kernel(
    const float* __restrict__ conn,      // (P, 512, 30)
    const float* __restrict__ r,
    const float* __restrict__ u,
    const float* __restrict__ v,
    const float* __restrict__ r_hpc,     // (P,)
    const float* __restrict__ r_bearing, // (30,)
    const float* __restrict__ pos_estimate,
    const float* __restrict__ angular_velocity,
    const float* __restrict__ sen2hd,
    const float* __restrict__ shared_t,
    float* __restrict__ out,
    int P)
{
    extern __shared__ float buf[];                 // DEPTH * SLAB_FLOATS
    __shared__ __align__(8) unsigned long long mbar[DEPTH];
    __shared__ int   s_pidx[DEPTH];
    __shared__ int   s_last;
    __shared__ float s_red[N_NEUR];
    __shared__ float s_rr[N_NEUR];
    __shared__ float s_cn[N_NEUR];

    const int tid = threadIdx.x;

    // rb into registers (uniform; compile-time indices)
    float rbv[NL];
    #pragma unroll
    for (int l = 0; l < NL; l++) rbv[l] = __ldg(r_bearing + l);

    // ticket state lives in thread 0's registers
    int cur = 0, rem = 0;

    if (tid == 0) {
        #pragma unroll
        for (int s = 0; s < DEPTH; s++) mbar_init(smem_u32(&mbar[s]), 1u);
        // preload up to DEPTH slabs
        for (int s = 0; s < DEPTH; s++) {
            if (rem == 0) {
                cur = atomicAdd(&g_ticket, TG);
                rem = (cur < P) ? min(TG, P - cur) : 0;
            }
            if (rem > 0) {
                s_pidx[s] = cur;
                bulk_load(smem_u32(buf + s * SLAB_FLOATS),
                          conn + (size_t)cur * SLAB_FLOATS,
                          SLAB_BYTES, smem_u32(&mbar[s]));
                cur++; rem--;
            } else {
                s_pidx[s] = -1;
            }
        }
    }
    __syncthreads();  // barriers + preload indices visible

    float acc  = 0.0f;
    float wsum = 0.0f;                    // thread 0 only: block's sum(r_hpc)
    for (int it = 0; ; it++) {
        const int s = it % DEPTH;
        const int p = s_pidx[s];          // written >= DEPTH-1 barriers ago
        if (p < 0) break;

        const float w = __ldg(r_hpc + p); // broadcast load, issues early
        if (tid == 0) wsum += w;          // p's are disjoint across blocks
        mbar_wait(smem_u32(&mbar[s]), (uint32_t)((it / DEPTH) & 1));

        const float2* row = (const float2*)(buf + s * SLAB_FLOATS) + tid * (NL / 2);
        float dot = 0.0f;
        #pragma unroll
        for (int l = 0; l < NL / 2; l++) {
            float2 v2 = row[l];
            dot = fmaf(v2.x, rbv[2 * l],     dot);
            dot = fmaf(v2.y, rbv[2 * l + 1], dot);
        }
        acc = fmaf(w, dot, acc);

        __syncthreads();                  // everyone done with buf[s]
        if (tid == 0) {
            if (rem == 0) {
                cur = atomicAdd(&g_ticket, TG);
                rem = (cur < P) ? min(TG, P - cur) : 0;
            }
            if (rem > 0) {
                s_pidx[s] = cur;
                bulk_load(smem_u32(buf + s * SLAB_FLOATS),
                          conn + (size_t)cur * SLAB_FLOATS,
                          SLAB_BYTES, smem_u32(&mbar[s]));
                cur++; rem--;
            } else {
                s_pidx[s] = -1;
            }
        }
    }

    // publish: coalesced float atomics, overlapped with others' streaming
    atomicAdd(&g_bearing[tid], acc);
    if (tid == 0) atomicAdd(&g_sum_hpc, wsum);
    __threadfence();
    __syncthreads();
    if (tid == 0) {
        int old = atomicAdd(&g_count, 1);
        s_last = (old == GRID - 1);
    }
    __syncthreads();
    if (!s_last) return;

    // ------------------- last block: small final stage -------------------
    __threadfence();  // acquire all blocks' contributions

    const int n = tid;

    const float bear    = g_bearing[n];   // all adds ordered before counter
    const float sum_hpc = g_sum_hpc;
    g_bearing[n] = 0.0f;                  // reset for next graph replay
                                          // (only this block is alive now)

    const float DX   = TWO_PI_F / 512.0f;
    const float J0   = 20.0f / 512.0f;
    const float KPAR = 0.8f / 512.0f * 20.0f;

    const float xn = -PI_F + n * DX;
    const float rn = r[n];
    s_rr[n] = rn;
    {
        float dj = period_bound(n * DX);
        float q  = dj / GW;
        s_cn[n] = J0 * expf(-0.5f * q * q) / (TWO_PI_F * GW * GW);
    }

    // bump center: angle(sum exp(i x) r)
    s_red[n] = cosf(xn) * rn;
    __syncthreads();
    #pragma unroll
    for (int off = 256; off > 0; off >>= 1) {
        if (n < off) s_red[n] += s_red[n + off];
        __syncthreads();
    }
    const float csum = s_red[0];
    __syncthreads();
    s_red[n] = sinf(xn) * rn;
    __syncthreads();
    #pragma unroll
    for (int off = 256; off > 0; off >>= 1) {
        if (n < off) s_red[n] += s_red[n + off];
        __syncthreads();
    }
    const float ssum = s_red[0];
    __syncthreads();
    const float center = atan2f(ssum, csum);

    // path integration (DT = 0.1 config constant, TAU_E = 1000)
    float pos = pos_estimate[0];
    float pe  = pos + (period_bound(center - pos) / 1000.0f + angular_velocity[0]) * 0.1f;
    pos = period_bound(pe);

    float dd = period_bound(xn - pos) / GW;
    const float motion = 3.0f * expf(-0.25f * dd * dd);

    // recurrent input: circular convolution
    float irec = 0.0f;
    #pragma unroll 8
    for (int m = 0; m < N_NEUR; m++)
        irec = fmaf(s_cn[m], s_rr[(n - m) & (N_NEUR - 1)], irec);

    const float ib = bear / sum_hpc;
    const float input_total = motion + irec + ib * sen2hd[0];

    // exact exponential ODE step for u (v1 never feeds the output)
    const float dt_ode = shared_t[1] - shared_t[0];
    const float C1 = input_total - v[n];
    const float u1 = C1 + (u[n] - C1) * expf(-dt_ode /* / TAU=1 */);

    const float un = u1 > 0.0f ? u1 : 0.0f;
    const float r1 = un * un;

    s_red[n] = r1;
    __syncthreads();
    #pragma unroll
    for (int off = 256; off > 0; off >>= 1) {
        if (n < off) s_red[n] += s_red[n + off];
        __syncthreads();
    }
    const float sum_r1 = s_red[0];

    out[n] = r1 / (1.0f + KPAR * sum_r1);

    // reset for next graph replay (all threads are past their g_sum_hpc read:
    // the block-wide reductions above synchronized the block)
    if (n == 0) { g_count = 0; g_ticket = 0; g_sum_hpc = 0.0f; }
}

// ---------------------------------------------------------------------------
// Launch
// ---------------------------------------------------------------------------
extern "C" void kernel_launch(void* const* d_in, const int* in_sizes, int n_in,
                              void* d_out, int out_size) {
    const float* conn      = (const float*)d_in[0];   // (P, 512, 30)
    const float* r         = (const float*)d_in[1];   // (512,)
    const float* u         = (const float*)d_in[2];   // (512,)
    const float* v         = (const float*)d_in[3];   // (512,)
    const float* r_hpc     = (const float*)d_in[4];   // (P,)
    const float* r_bearing = (const float*)d_in[5];   // (30,)
    const float* pos_est   = (const float*)d_in[6];   // (1,)
    const float* ang_vel   = (const float*)d_in[7];   // (1,)
    // d_in[8] = HD, unused (get_HD = 0 path)
    const float* sen2hd    = (const float*)d_in[9];   // (1,)
    const float* shared_t  = (const float*)d_in[10];  // (2,)
    float* out = (float*)d_out;

    const int P = in_sizes[4];  // r_hpc length

    const int smem_bytes = DEPTH * SLAB_BYTES;  // 184320 per block
    cudaFuncSetAttribute(fused_kernel,
                         cudaFuncAttributeMaxDynamicSharedMemorySize, smem_bytes);

    fused_kernel<<<GRID, N_NEUR, smem_bytes>>>(
        conn, r, u, v, r_hpc, r_bearing, pos_est, ang_vel, sen2hd, shared_t,
        out, P);
}